// round 15
// baseline (speedup 1.0000x reference)
#include <cuda_runtime.h>
#include <cuda_fp16.h>
#include <stdint.h>
#include <math.h>

// Problem constants
#define D        256
#define NE       8192
#define T_TOTAL  32768
#define BETA     0.25f

// GEMM tiling (fp16 inputs, fp32 accum, K=256)
#define BM       128           // tokens per CTA
#define BN       128           // codes per chunk
#define STG_KS   4             // ksteps per B stage
#define NCHUNK   64            // NE / BN
#define NIT      256           // NCHUNK * 4 stages
#define THREADS  256
#define NBLK     (T_TOTAL / BM)   // 256

#define SA_BYTES (8 * 16 * 32 * 16)    // 65536
#define SB_BYTES (16 * 4 * 32 * 8)     // 16384

#define ESCALE   16384.0f              // 2^14 emb prescale (exact)
#define DESCALE  0.0001220703125f      // 2^-13

#define CAP      64

// Scratch (device globals; no runtime allocation)
__device__ uint2  g_eb[1024 * 512];                 // 4 MB:  B frags
__device__ __half g_m2[(size_t)T_TOTAL * NE];       // 512 MB: approx 2*dot
__device__ float  g_partial[NBLK];

// ---------------------------------------------------------------------------
__device__ __forceinline__ uint32_t smem_u32(const void* p) {
    uint32_t a;
    asm("{ .reg .u64 t; cvta.to.shared.u64 t, %1; cvt.u32.u64 %0, t; }" : "=r"(a) : "l"(p));
    return a;
}
__device__ __forceinline__ void cp_async16(uint32_t dst, const void* src) {
    asm volatile("cp.async.cg.shared.global [%0], [%1], 16;" :: "r"(dst), "l"(src));
}
__device__ __forceinline__ void cp_commit() {
    asm volatile("cp.async.commit_group;" ::: "memory");
}
__device__ __forceinline__ void cp_wait1() {
    asm volatile("cp.async.wait_group 1;" ::: "memory");
}
__device__ __forceinline__ void cp_wait0() {
    asm volatile("cp.async.wait_group 0;" ::: "memory");
}
__device__ __forceinline__ void mma_f16(float* c, const uint4 a, uint32_t b0, uint32_t b1) {
    asm volatile(
        "mma.sync.aligned.m16n8k16.row.col.f32.f16.f16.f32 "
        "{%0,%1,%2,%3}, {%4,%5,%6,%7}, {%8,%9}, {%0,%1,%2,%3};"
        : "+f"(c[0]), "+f"(c[1]), "+f"(c[2]), "+f"(c[3])
        : "r"(a.x), "r"(a.y), "r"(a.z), "r"(a.w), "r"(b0), "r"(b1));
}
__device__ __forceinline__ float ulp_of(float x) {
    return __uint_as_float(((__float_as_uint(x) >> 23) - 23) << 23);
}
__device__ __forceinline__ uint32_t pack_h2(float a, float b) {
    __half2 h = __floats2half2_rn(a, b);
    return *reinterpret_cast<uint32_t*>(&h);
}

// ---------------------------------------------------------------------------
// Prep B: emb * 2^14 -> fp16 mma-B fragments. [h][ks][lane] uint2.
// ---------------------------------------------------------------------------
__global__ void vq_prep_e(const float* __restrict__ emb) {
    int h = blockIdx.x;                 // 0..1023
    int tid = threadIdx.x;
    uint2* out = g_eb + (size_t)h * 512;
#pragma unroll
    for (int it = 0; it < 2; it++) {
        int idx = tid + it * THREADS;
        int ks = idx >> 5, l = idx & 31;
        int gid = l >> 2, tig = l & 3;
        int kb = ks * 16 + 2 * tig;
        const float* r = emb + (size_t)(h * 8 + gid) * D;
        float2 p0 = *(const float2*)(r + kb);
        float2 p1 = *(const float2*)(r + kb + 8);
        uint2 v;
        v.x = pack_h2(p0.x * ESCALE, p0.y * ESCALE);
        v.y = pack_h2(p1.x * ESCALE, p1.y * ESCALE);
        out[idx] = v;
    }
}

// ---------------------------------------------------------------------------
// Fused: A-prep + norms + GEMM + (pick + gather + loss partial).
// Each CTA owns 128 tokens end-to-end.
// ---------------------------------------------------------------------------
extern __shared__ char smem_raw[];

__global__ void __launch_bounds__(THREADS, 2)
vq_fused(const float* __restrict__ z, const float* __restrict__ emb,
         float* __restrict__ out_zq, float* __restrict__ out_idx_f) {
    const int tid  = threadIdx.x;
    const int lane = tid & 31;
    const int wid  = tid >> 5;
    const int wm   = wid >> 1;          // 0..3
    const int wn   = wid & 1;           // 0..1
    const int gid  = lane >> 2;
    const int tig  = lane & 3;
    const int t0   = blockIdx.x * BM;

    __shared__ float s_z2[BM];
    __shared__ float s_az[BM];
    __shared__ float s_mx[BM];
    __shared__ int   s_list[8][CAP];
    __shared__ int   s_cnt[8];
    __shared__ float s_ws[8];

    char* sA = smem_raw;
    char* sB[2] = { smem_raw + SA_BYTES, smem_raw + SA_BYTES + SB_BYTES };
    uint32_t sBu[2] = { smem_u32(sB[0]), smem_u32(sB[1]) };

    // ---- Phase 0: build A fragments in smem directly from z ----
#pragma unroll
    for (int it2 = 0; it2 < 16; it2++) {
        int idx = tid + it2 * THREADS;   // 0..4095
        int mg  = idx >> 9;              // 0..7
        int rem = idx & 511;
        int ks  = rem >> 5, l = rem & 31;
        int gd  = l >> 2, tg = l & 3;
        int kb  = ks * 16 + 2 * tg;
        const float* r0 = z + (size_t)(t0 + mg * 16 + gd) * D;
        const float* r1 = r0 + 8 * D;
        float2 p0 = *(const float2*)(r0 + kb);
        float2 p1 = *(const float2*)(r1 + kb);
        float2 p2 = *(const float2*)(r0 + kb + 8);
        float2 p3 = *(const float2*)(r1 + kb + 8);
        uint4 v;
        v.x = pack_h2(p0.x, p0.y);
        v.y = pack_h2(p1.x, p1.y);
        v.z = pack_h2(p2.x, p2.y);
        v.w = pack_h2(p3.x, p3.y);
        *(uint4*)(sA + (((mg * 16 + ks) * 32 + l) << 4)) = v;
    }
    // ---- norms for this CTA's tokens (z rows L1-hot) ----
    for (int j = 0; j < 16; j++) {
        int tl = wid * 16 + j;
        const float* row = z + (size_t)(t0 + tl) * D;
        float s2 = 0.f, sa = 0.f;
#pragma unroll
        for (int i = 0; i < D / 32; i++) {
            float v = row[lane + 32 * i];
            s2 = fmaf(v, v, s2);
            sa += fabsf(v);
        }
#pragma unroll
        for (int o = 16; o; o >>= 1) {
            s2 += __shfl_xor_sync(0xffffffffu, s2, o);
            sa += __shfl_xor_sync(0xffffffffu, sa, o);
        }
        if (lane == 0) { s_z2[tl] = s2; s_az[tl] = sa; }
    }

    // ---- Phase 1: GEMM ----
    const char* gE = (const char*)g_eb;
    auto fillB = [&](int buf, int it) {
        int chunk = it >> 2, s = it & 3;
#pragma unroll
        for (int j = 0; j < 4; j++) {
            int f = tid + j * THREADS;         // 0..1023 (16B units)
            int hl = f >> 6, rem = f & 63;
            int ksl = rem >> 4, w = rem & 15;
            const char* src = gE + ((size_t)(chunk * 16 + hl) * 4096
                                    + (s * STG_KS + ksl) * 256 + w * 16);
            cp_async16(sBu[buf] + (hl * STG_KS + ksl) * 256 + w * 16, src);
        }
    };
    fillB(0, 0); cp_commit();
    fillB(1, 1); cp_commit();

    float acc[2][8][4];
    float rmx[2][2] = { {-3.0e38f, -3.0e38f}, {-3.0e38f, -3.0e38f} };

    for (int it = 0; it < NIT; it++) {
        const int chunk = it >> 2, s = it & 3, buf = it & 1;
        if (it + 1 < NIT) cp_wait1(); else cp_wait0();
        __syncthreads();

        if (s == 0) {
#pragma unroll
            for (int im = 0; im < 2; im++)
#pragma unroll
                for (int in = 0; in < 8; in++)
#pragma unroll
                    for (int q = 0; q < 4; q++) acc[im][in][q] = 0.f;
        }

        const char* pB = sB[buf];
#pragma unroll
        for (int ksl = 0; ksl < STG_KS; ksl++) {
            int ks = s * STG_KS + ksl;
            uint4 a[2];
#pragma unroll
            for (int im = 0; im < 2; im++) {
                int mg = wm * 2 + im;
                a[im] = *(const uint4*)(sA + (((mg * 16 + ks) * 32 + lane) << 4));
            }
#pragma unroll
            for (int in = 0; in < 8; in++) {
                int hl = wn * 8 + in;
                uint2 b = *(const uint2*)(pB + (((hl * STG_KS + ksl) * 32 + lane) << 3));
#pragma unroll
                for (int im = 0; im < 2; im++)
                    mma_f16(acc[im][in], a[im], b.x, b.y);
            }
        }
        __syncthreads();
        if (it + 2 < NIT) { fillB(buf, it + 2); cp_commit(); }

        if (s == 3) {
#pragma unroll
            for (int im = 0; im < 2; im++)
#pragma unroll
                for (int h = 0; h < 2; h++) {
                    int trow = t0 + (wm * 2 + im) * 16 + h * 8 + gid;
                    __half* dst = g_m2 + (size_t)trow * NE + chunk * 128 + wn * 64 + 2 * tig;
#pragma unroll
                    for (int in = 0; in < 8; in++) {
                        float2 f2;
                        f2.x = acc[im][in][h * 2 + 0] * DESCALE;
                        f2.y = acc[im][in][h * 2 + 1] * DESCALE;
                        rmx[im][h] = fmaxf(rmx[im][h], fmaxf(f2.x, f2.y));
                        *(__half2*)(dst + in * 8) = __float22half2_rn(f2);
                    }
                }
        }
    }

    // ---- per-token max into s_mx ----
    __syncthreads();
    float* smx = (float*)smem_raw;       // reuse sA area: [2][128]
#pragma unroll
    for (int im = 0; im < 2; im++)
#pragma unroll
        for (int h = 0; h < 2; h++) {
            float m = rmx[im][h];
#pragma unroll
            for (int o = 1; o <= 2; o <<= 1)
                m = fmaxf(m, __shfl_xor_sync(0xffffffffu, m, o));
            if (tig == 0) {
                int trl = (wm * 2 + im) * 16 + h * 8 + gid;
                smx[wn * 128 + trl] = m;
            }
        }
    __syncthreads();
    for (int trl = tid; trl < BM; trl += THREADS)
        s_mx[trl] = fmaxf(smx[trl], smx[128 + trl]);
    __syncthreads();

    // ---- Phase 2: pick + gather per token (warp-owned, 16 tokens/warp) ----
    float* sz = (float*)(smem_raw + wid * 1024);   // per-warp z row (256 floats)
    float lsum = 0.f;                              // loss partial per lane

    for (int j = 0; j < 16; j++) {
        const int tl = wid * 16 + j;
        const int t  = t0 + tl;

        {
            float4* dst = (float4*)sz;
            const float4* src = (const float4*)(z + (size_t)t * D);
            dst[lane] = src[lane];
            dst[lane + 32] = src[lane + 32];
        }
        if (lane == 0) s_cnt[wid] = 0;
        __syncwarp();

        const float z2 = s_z2[tl];
        const float az = s_az[tl];
        // hard bound (fp32 accum): conversion + fp16 store + slack (validated)
        const float eps_a = 0.001953125f * 1.2207031e-4f * az + 8.2e-6f;
        const float M   = ulp_of(z2) + 2.0f * eps_a + 1.7e-5f;
        const float thr = s_mx[tl] - M;

        const uint4* r4 = (const uint4*)(g_m2 + (size_t)t * NE);
#pragma unroll 4
        for (int jj = 0; jj < 32; jj++) {
            uint4 v = r4[jj * 32 + lane];
            const __half2* hp = (const __half2*)&v;
            int ebase = (jj * 32 + lane) * 8;
#pragma unroll
            for (int p = 0; p < 4; p++) {
                float2 f = __half22float2(hp[p]);
                if (f.x >= thr) {
                    int pos = atomicAdd(&s_cnt[wid], 1);
                    if (pos < CAP) s_list[wid][pos] = ebase + p * 2;
                }
                if (f.y >= thr) {
                    int pos = atomicAdd(&s_cnt[wid], 1);
                    if (pos < CAP) s_list[wid][pos] = ebase + p * 2 + 1;
                }
            }
        }
        __syncwarp();
        int cnt = s_cnt[wid];

        float bv = 3.0e38f;
        int   bi = 0x7fffffff;

        if (cnt <= CAP) {
            for (int base = 0; base < cnt; base += 32) {
                int ci = base + lane;
                float dv = 3.0e38f;
                int   e  = 0x7fffffff;
                if (ci < cnt) {
                    e = s_list[wid][ci];
                    const float* er = emb + (size_t)e * D;
                    float d = 0.f;
#pragma unroll 8
                    for (int k = 0; k < D; k++) d = fmaf(sz[k], er[k], d);
                    dv = __fadd_rn(z2, -__fmul_rn(2.f, d));
                }
                if (dv < bv || (dv == bv && e < bi)) { bv = dv; bi = e; }
            }
        } else {
            // overflow fallback: exact full scan (codes ascending per lane)
            for (int c = 0; c < 256; c++) {
                int e = lane * 256 + c;
                const float* er = emb + (size_t)e * D;
                float d = 0.f;
#pragma unroll 8
                for (int k = 0; k < D; k++) d = fmaf(sz[k], er[k], d);
                float dv = __fadd_rn(z2, -__fmul_rn(2.f, d));
                if (dv < bv) { bv = dv; bi = e; }
            }
        }
#pragma unroll
        for (int o = 16; o; o >>= 1) {
            float ov = __shfl_xor_sync(0xffffffffu, bv, o);
            int   oi = __shfl_xor_sync(0xffffffffu, bi, o);
            if (ov < bv || (ov == bv && oi < bi)) { bv = ov; bi = oi; }
        }
        bi = __shfl_sync(0xffffffffu, bi, 0);
        if (lane == 0) out_idx_f[t] = (float)bi;

        // gather + STE + loss (z row already in smem)
        {
            const float* er = emb + (size_t)bi * D;
            float* o = out_zq + (size_t)t * D;
#pragma unroll
            for (int i = 0; i < D / 32; i++) {
                int c = lane + 32 * i;
                float q  = er[c];
                float zc = sz[c];
                float d  = __fadd_rn(q, -zc);
                lsum = fmaf(d, d, lsum);
                o[c] = __fadd_rn(zc, d);
            }
        }
    }

    // ---- loss partial per CTA ----
#pragma unroll
    for (int o = 16; o; o >>= 1) lsum += __shfl_xor_sync(0xffffffffu, lsum, o);
    if (lane == 0) s_ws[wid] = lsum;
    __syncthreads();
    if (tid == 0) {
        float tsum = 0.f;
#pragma unroll
        for (int i = 0; i < 8; i++) tsum += s_ws[i];
        g_partial[blockIdx.x] = tsum;
    }
}

// ---------------------------------------------------------------------------
__global__ void vq_finalize_kernel(float* __restrict__ out_loss) {
    int tid = threadIdx.x;             // 256 threads, NBLK=256 partials
    double s = (double)g_partial[tid];
#pragma unroll
    for (int o = 16; o; o >>= 1) s += __shfl_xor_sync(0xffffffffu, s, o);
    __shared__ double ws[8];
    if ((tid & 31) == 0) ws[tid >> 5] = s;
    __syncthreads();
    if (tid == 0) {
        double t = 0.0;
#pragma unroll
        for (int i = 0; i < 8; i++) t += ws[i];
        *out_loss = (float)((1.0 + (double)BETA) * t / (double)((size_t)T_TOTAL * D));
    }
}

// ---------------------------------------------------------------------------
extern "C" void kernel_launch(void* const* d_in, const int* in_sizes, int n_in,
                              void* d_out, int out_size) {
    const float* z   = (const float*)d_in[0];   // [8,4096,256] fp32
    const float* emb = (const float*)d_in[1];   // [8192,256] fp32
    float* out       = (float*)d_out;
    float* out_zq    = out;
    float* out_loss  = out + (size_t)T_TOTAL * D;
    float* out_idx   = out + (size_t)T_TOTAL * D + 1;

    vq_prep_e<<<1024, THREADS>>>(emb);

    size_t smem_bytes = SA_BYTES + 2 * SB_BYTES;   // 98304 dynamic
    cudaFuncSetAttribute(vq_fused,
                         cudaFuncAttributeMaxDynamicSharedMemorySize,
                         (int)smem_bytes);
    vq_fused<<<NBLK, THREADS, smem_bytes>>>(z, emb, out_zq, out_idx);

    vq_finalize_kernel<<<1, 256>>>(out_loss);
}

// round 16
// speedup vs baseline: 1.6111x; 1.6111x over previous
#include <cuda_runtime.h>
#include <cuda_fp16.h>
#include <stdint.h>
#include <math.h>

// Problem constants
#define D        256
#define NE       8192
#define T_TOTAL  32768
#define BETA     0.25f

// GEMM tiling (fp16 inputs, fp32 accum, K=256)
#define BM       128
#define BN       128
#define STG_KS   4
#define NIT      256           // 64 chunks * 4 stages
#define THREADS  256

#define SA_BYTES (8 * 16 * 32 * 16)    // 65536
#define SB_BYTES (16 * 4 * 32 * 8)     // 16384

#define ESCALE   16384.0f              // 2^14 emb prescale (exact)
#define DESCALE  0.0001220703125f      // 2^-13

#define NC       32                    // per-(token,owner) candidate capacity

// Scratch (device globals; no runtime allocation)
__device__ uint4  g_za[2048 * 512];                    // 16 MB: A frags
__device__ uint2  g_eb[1024 * 512];                    // 4 MB:  B frags
__device__ int2   g_cand[(size_t)T_TOTAL * 8 * NC];    // 64 MB: (m2 bits, e)
__device__ int    g_ccnt[T_TOTAL * 8];
__device__ float  g_rmax[T_TOTAL * 8];
__device__ float  g_z2[T_TOTAL];
__device__ float  g_az[T_TOTAL];
__device__ float  g_partial[4096];

// ---------------------------------------------------------------------------
__device__ __forceinline__ uint32_t smem_u32(const void* p) {
    uint32_t a;
    asm("{ .reg .u64 t; cvta.to.shared.u64 t, %1; cvt.u32.u64 %0, t; }" : "=r"(a) : "l"(p));
    return a;
}
__device__ __forceinline__ void cp_async16(uint32_t dst, const void* src) {
    asm volatile("cp.async.cg.shared.global [%0], [%1], 16;" :: "r"(dst), "l"(src));
}
__device__ __forceinline__ void cp_commit() {
    asm volatile("cp.async.commit_group;" ::: "memory");
}
__device__ __forceinline__ void cp_wait1() {
    asm volatile("cp.async.wait_group 1;" ::: "memory");
}
__device__ __forceinline__ void cp_wait0() {
    asm volatile("cp.async.wait_group 0;" ::: "memory");
}
__device__ __forceinline__ void mma_f16(float* c, const uint4 a, uint32_t b0, uint32_t b1) {
    asm volatile(
        "mma.sync.aligned.m16n8k16.row.col.f32.f16.f16.f32 "
        "{%0,%1,%2,%3}, {%4,%5,%6,%7}, {%8,%9}, {%0,%1,%2,%3};"
        : "+f"(c[0]), "+f"(c[1]), "+f"(c[2]), "+f"(c[3])
        : "r"(a.x), "r"(a.y), "r"(a.z), "r"(a.w), "r"(b0), "r"(b1));
}
__device__ __forceinline__ float ulp_of(float x) {
    return __uint_as_float(((__float_as_uint(x) >> 23) - 23) << 23);
}
__device__ __forceinline__ uint32_t pack_h2(float a, float b) {
    __half2 h = __floats2half2_rn(a, b);
    return *reinterpret_cast<uint32_t*>(&h);
}
// hard-bound margin (validated in rounds 10/12/14)
__device__ __forceinline__ float margin_of(float z2, float az) {
    float eps_a = 0.001953125f * 1.2207031e-4f * az + 8.2e-6f;
    return ulp_of(z2) + 2.0f * eps_a + 1.7e-5f;
}

// ---------------------------------------------------------------------------
// Prep A: z -> fp16 mma-A fragments. [g][ks][lane] uint4.
// ---------------------------------------------------------------------------
__global__ void vq_prep_z(const float* __restrict__ z) {
    int g = blockIdx.x;                 // 0..2047
    int tid = threadIdx.x;
    uint4* out = g_za + (size_t)g * 512;
#pragma unroll
    for (int it = 0; it < 2; it++) {
        int idx = tid + it * THREADS;
        int ks = idx >> 5, l = idx & 31;
        int gid = l >> 2, tig = l & 3;
        int kb = ks * 16 + 2 * tig;
        const float* r0 = z + (size_t)(g * 16 + gid) * D;
        const float* r1 = r0 + 8 * D;
        float2 p0 = *(const float2*)(r0 + kb);
        float2 p1 = *(const float2*)(r1 + kb);
        float2 p2 = *(const float2*)(r0 + kb + 8);
        float2 p3 = *(const float2*)(r1 + kb + 8);
        uint4 v;
        v.x = pack_h2(p0.x, p0.y);
        v.y = pack_h2(p1.x, p1.y);
        v.z = pack_h2(p2.x, p2.y);
        v.w = pack_h2(p3.x, p3.y);
        out[idx] = v;
    }
}

// ---------------------------------------------------------------------------
// Prep B: emb * 2^14 -> fp16 mma-B fragments. [h][ks][lane] uint2.
// ---------------------------------------------------------------------------
__global__ void vq_prep_e(const float* __restrict__ emb) {
    int h = blockIdx.x;                 // 0..1023
    int tid = threadIdx.x;
    uint2* out = g_eb + (size_t)h * 512;
#pragma unroll
    for (int it = 0; it < 2; it++) {
        int idx = tid + it * THREADS;
        int ks = idx >> 5, l = idx & 31;
        int gid = l >> 2, tig = l & 3;
        int kb = ks * 16 + 2 * tig;
        const float* r = emb + (size_t)(h * 8 + gid) * D;
        float2 p0 = *(const float2*)(r + kb);
        float2 p1 = *(const float2*)(r + kb + 8);
        uint2 v;
        v.x = pack_h2(p0.x * ESCALE, p0.y * ESCALE);
        v.y = pack_h2(p1.x * ESCALE, p1.y * ESCALE);
        out[idx] = v;
    }
}

// ---------------------------------------------------------------------------
// Token norms: z2 = sum z^2, az = sum |z|. One warp per token.
// ---------------------------------------------------------------------------
__global__ void vq_norms(const float* __restrict__ z) {
    int t = (blockIdx.x * blockDim.x + threadIdx.x) >> 5;
    int lane = threadIdx.x & 31;
    if (t >= T_TOTAL) return;
    const float* row = z + (size_t)t * D;
    float s2 = 0.f, sa = 0.f;
#pragma unroll
    for (int i = 0; i < D / 32; i++) {
        float v = row[lane + 32 * i];
        s2 = fmaf(v, v, s2);
        sa += fabsf(v);
    }
#pragma unroll
    for (int o = 16; o; o >>= 1) {
        s2 += __shfl_xor_sync(0xffffffffu, s2, o);
        sa += __shfl_xor_sync(0xffffffffu, sa, o);
    }
    if (lane == 0) { g_z2[t] = s2; g_az[t] = sa; }
}

// ---------------------------------------------------------------------------
// GEMM + in-epilogue candidate collection. No m2 matrix store at all.
// Each thread owns 4 token rows (im x h); owner lane = wn*4 + tig (8 owners
// per token). Running-max threshold with hard margin M guarantees every
// possible argmin candidate lands in some owner's buffer (or overflow flag).
// ---------------------------------------------------------------------------
extern __shared__ char smem_raw[];

__global__ void __launch_bounds__(THREADS, 2)
vq_gemm(void) {
    const int tid  = threadIdx.x;
    const int lane = tid & 31;
    const int wid  = tid >> 5;
    const int wm   = wid >> 1;
    const int wn   = wid & 1;
    const int gid  = lane >> 2;
    const int tig  = lane & 3;
    const int t0   = blockIdx.x * BM;
    const int owner = wn * 4 + tig;

    char* sA = smem_raw;
    char* sB[2] = { smem_raw + SA_BYTES, smem_raw + SA_BYTES + SB_BYTES };
    uint32_t sAu = smem_u32(sA);
    uint32_t sBu[2] = { smem_u32(sB[0]), smem_u32(sB[1]) };

    // load A (64 KB) once
    {
        const uint4* gA = g_za + (size_t)blockIdx.x * 8 * 512;
#pragma unroll
        for (int j = 0; j < 16; j++) {
            int f = tid + j * THREADS;
            cp_async16(sAu + f * 16, gA + f);
        }
    }
    const char* gE = (const char*)g_eb;
    auto fillB = [&](int buf, int it) {
        int chunk = it >> 2, s = it & 3;
#pragma unroll
        for (int j = 0; j < 4; j++) {
            int f = tid + j * THREADS;
            int hl = f >> 6, rem = f & 63;
            int ksl = rem >> 4, w = rem & 15;
            const char* src = gE + ((size_t)(chunk * 16 + hl) * 4096
                                    + (s * STG_KS + ksl) * 256 + w * 16);
            cp_async16(sBu[buf] + (hl * STG_KS + ksl) * 256 + w * 16, src);
        }
    };
    fillB(0, 0); cp_commit();
    fillB(1, 1); cp_commit();

    // per-owned-row filter state (4 rows: idx = im*2+h)
    float rmax4[4] = {-3.0e38f, -3.0e38f, -3.0e38f, -3.0e38f};
    float thr4[4]  = {-3.0e38f, -3.0e38f, -3.0e38f, -3.0e38f};
    float M4[4];
    int   cnt4[4]  = {0, 0, 0, 0};
    size_t base4[4];
#pragma unroll
    for (int im = 0; im < 2; im++)
#pragma unroll
        for (int h = 0; h < 2; h++) {
            int trow = t0 + (wm * 2 + im) * 16 + h * 8 + gid;
            M4[im * 2 + h] = margin_of(g_z2[trow], g_az[trow]);
            base4[im * 2 + h] = ((size_t)trow * 8 + owner) * NC;
        }

    float acc[2][8][4];

    for (int it = 0; it < NIT; it++) {
        const int chunk = it >> 2, s = it & 3, buf = it & 1;
        if (it + 1 < NIT) cp_wait1(); else cp_wait0();
        __syncthreads();

        if (s == 0) {
#pragma unroll
            for (int im = 0; im < 2; im++)
#pragma unroll
                for (int in = 0; in < 8; in++)
#pragma unroll
                    for (int q = 0; q < 4; q++) acc[im][in][q] = 0.f;
        }

        const char* pB = sB[buf];
#pragma unroll
        for (int ksl = 0; ksl < STG_KS; ksl++) {
            int ks = s * STG_KS + ksl;
            uint4 a[2];
#pragma unroll
            for (int im = 0; im < 2; im++) {
                int mg = wm * 2 + im;
                a[im] = *(const uint4*)(sA + (((mg * 16 + ks) * 32 + lane) << 4));
            }
#pragma unroll
            for (int in = 0; in < 8; in++) {
                int hl = wn * 8 + in;
                uint2 b = *(const uint2*)(pB + (((hl * STG_KS + ksl) * 32 + lane) << 3));
#pragma unroll
                for (int im = 0; im < 2; im++)
                    mma_f16(acc[im][in], a[im], b.x, b.y);
            }
        }
        __syncthreads();
        if (it + 2 < NIT) { fillB(buf, it + 2); cp_commit(); }

        if (s == 3) {
            // epilogue: candidate filter (replaces m2 store)
            const int ecbase = chunk * 128 + wn * 64 + 2 * tig;
#pragma unroll
            for (int im = 0; im < 2; im++)
#pragma unroll
                for (int h = 0; h < 2; h++) {
                    const int r = im * 2 + h;
#pragma unroll
                    for (int in = 0; in < 8; in++) {
                        float m0 = acc[im][in][h * 2 + 0] * DESCALE;
                        float m1 = acc[im][in][h * 2 + 1] * DESCALE;
                        int e0 = ecbase + in * 8;
                        if (m0 >= thr4[r]) {
                            if (cnt4[r] < NC)
                                g_cand[base4[r] + cnt4[r]] =
                                    make_int2(__float_as_int(m0), e0);
                            cnt4[r]++;
                            if (m0 > rmax4[r]) { rmax4[r] = m0; thr4[r] = m0 - M4[r]; }
                        }
                        if (m1 >= thr4[r]) {
                            if (cnt4[r] < NC)
                                g_cand[base4[r] + cnt4[r]] =
                                    make_int2(__float_as_int(m1), e0 + 1);
                            cnt4[r]++;
                            if (m1 > rmax4[r]) { rmax4[r] = m1; thr4[r] = m1 - M4[r]; }
                        }
                    }
                }
        }
    }

    // publish per-owner state
#pragma unroll
    for (int im = 0; im < 2; im++)
#pragma unroll
        for (int h = 0; h < 2; h++) {
            const int r = im * 2 + h;
            int trow = t0 + (wm * 2 + im) * 16 + h * 8 + gid;
            g_ccnt[trow * 8 + owner] = cnt4[r];
            g_rmax[trow * 8 + owner] = rmax4[r];
        }
}

// ---------------------------------------------------------------------------
// Pick + gather + loss: warp per token. Reads only the tiny candidate lists.
// ---------------------------------------------------------------------------
#define PCAP (8 * NC)
__global__ void __launch_bounds__(256, 1)
vq_pick(const float* __restrict__ z, const float* __restrict__ emb,
        float* __restrict__ out_zq, float* __restrict__ out_idx_f) {
    __shared__ float sz[8][D];
    __shared__ int   slist[8][PCAP];
    __shared__ int   scnt[8];
    __shared__ float sws[8];
    const int w    = threadIdx.x >> 5;
    const int lane = threadIdx.x & 31;
    const int t    = blockIdx.x * 8 + w;

    {
        float4* dst = (float4*)sz[w];
        const float4* src = (const float4*)(z + (size_t)t * D);
        dst[lane] = src[lane];
        dst[lane + 32] = src[lane + 32];
    }
    if (lane == 0) scnt[w] = 0;
    __syncwarp();

    // global max + overflow check over the 8 owners
    float r = (lane < 8) ? g_rmax[t * 8 + lane] : -3.0e38f;
    int   c = (lane < 8) ? g_ccnt[t * 8 + lane] : 0;
#pragma unroll
    for (int o = 16; o; o >>= 1) r = fmaxf(r, __shfl_xor_sync(0xffffffffu, r, o));
    bool ovf = __any_sync(0xffffffffu, c > NC);

    const float z2 = g_z2[t];
    const float thr = r - margin_of(z2, g_az[t]);

    if (!ovf && lane < 8) {
        const int2* src = g_cand + ((size_t)t * 8 + lane) * NC;
        for (int i = 0; i < c; i++) {
            int2 cd = src[i];
            if (__int_as_float(cd.x) >= thr) {
                int pos = atomicAdd(&scnt[w], 1);
                slist[w][pos] = cd.y;
            }
        }
    }
    __syncwarp();
    int cnt = scnt[w];

    float bv = 3.0e38f;
    int   bi = 0x7fffffff;
    const float* zz = sz[w];

    if (!ovf) {
        for (int base = 0; base < cnt; base += 32) {
            int ci = base + lane;
            float dv = 3.0e38f;
            int   e  = 0x7fffffff;
            if (ci < cnt) {
                e = slist[w][ci];
                const float* er = emb + (size_t)e * D;
                float d = 0.f;
#pragma unroll 8
                for (int k = 0; k < D; k++) d = fmaf(zz[k], er[k], d);
                dv = __fadd_rn(z2, -__fmul_rn(2.f, d));
            }
            if (dv < bv || (dv == bv && e < bi)) { bv = dv; bi = e; }
        }
    } else {
        // overflow fallback: exact full scan (codes ascending per lane)
        for (int cc = 0; cc < 256; cc++) {
            int e = lane * 256 + cc;
            const float* er = emb + (size_t)e * D;
            float d = 0.f;
#pragma unroll 8
            for (int k = 0; k < D; k++) d = fmaf(zz[k], er[k], d);
            float dv = __fadd_rn(z2, -__fmul_rn(2.f, d));
            if (dv < bv) { bv = dv; bi = e; }
        }
    }
#pragma unroll
    for (int o = 16; o; o >>= 1) {
        float ov = __shfl_xor_sync(0xffffffffu, bv, o);
        int   oi = __shfl_xor_sync(0xffffffffu, bi, o);
        if (ov < bv || (ov == bv && oi < bi)) { bv = ov; bi = oi; }
    }
    bi = __shfl_sync(0xffffffffu, bi, 0);
    if (lane == 0) out_idx_f[t] = (float)bi;

    // gather + STE-exact output + loss partial
    float lsum = 0.f;
    {
        const float* er = emb + (size_t)bi * D;
        float* o = out_zq + (size_t)t * D;
#pragma unroll
        for (int i = 0; i < D / 32; i++) {
            int cc = lane + 32 * i;
            float q  = er[cc];
            float zc = zz[cc];
            float d  = __fadd_rn(q, -zc);
            lsum = fmaf(d, d, lsum);
            o[cc] = __fadd_rn(zc, d);
        }
    }
#pragma unroll
    for (int o = 16; o; o >>= 1) lsum += __shfl_xor_sync(0xffffffffu, lsum, o);
    if (lane == 0) sws[w] = lsum;
    __syncthreads();
    if (threadIdx.x == 0) {
        float tsum = 0.f;
#pragma unroll
        for (int i = 0; i < 8; i++) tsum += sws[i];
        g_partial[blockIdx.x] = tsum;
    }
}

// ---------------------------------------------------------------------------
__global__ void vq_finalize_kernel(float* __restrict__ out_loss) {
    int tid = threadIdx.x;             // 256 threads, 4096 partials
    double s = 0.0;
#pragma unroll
    for (int i = 0; i < 16; i++) s += (double)g_partial[tid + 256 * i];
#pragma unroll
    for (int o = 16; o; o >>= 1) s += __shfl_xor_sync(0xffffffffu, s, o);
    __shared__ double ws[8];
    if ((tid & 31) == 0) ws[tid >> 5] = s;
    __syncthreads();
    if (tid == 0) {
        double t = 0.0;
#pragma unroll
        for (int i = 0; i < 8; i++) t += ws[i];
        *out_loss = (float)((1.0 + (double)BETA) * t / (double)((size_t)T_TOTAL * D));
    }
}

// ---------------------------------------------------------------------------
extern "C" void kernel_launch(void* const* d_in, const int* in_sizes, int n_in,
                              void* d_out, int out_size) {
    const float* z   = (const float*)d_in[0];   // [8,4096,256] fp32
    const float* emb = (const float*)d_in[1];   // [8192,256] fp32
    float* out       = (float*)d_out;
    float* out_zq    = out;
    float* out_loss  = out + (size_t)T_TOTAL * D;
    float* out_idx   = out + (size_t)T_TOTAL * D + 1;

    vq_prep_z<<<2048, THREADS>>>(z);
    vq_prep_e<<<1024, THREADS>>>(emb);
    vq_norms<<<T_TOTAL / 8, 256>>>(z);

    size_t smem_bytes = SA_BYTES + 2 * SB_BYTES;   // 98304
    cudaFuncSetAttribute(vq_gemm,
                         cudaFuncAttributeMaxDynamicSharedMemorySize,
                         (int)smem_bytes);
    vq_gemm<<<T_TOTAL / BM, THREADS, smem_bytes>>>();

    vq_pick<<<T_TOTAL / 8, 256>>>(z, emb, out_zq, out_idx);
    vq_finalize_kernel<<<1, 256>>>(out_loss);
}